// round 4
// baseline (speedup 1.0000x reference)
#include <cuda_runtime.h>
#include <cstdint>

// Problem constants (fixed shapes from setup_inputs)
#define N_PTS   20000
#define C_FEAT  64
#define BATCH   2
#define NQ_P    2048
#define NSAMP   32
#define C_OUT   (3 + C_FEAT)          // 67
#define NQ      (BATCH * NQ_P)        // 4096
#define NC      12                    // grid cells per dim, cell = 1/12 >= radius
#define NCELLS  (NC * NC * NC)        // 1728
#define CAND_MAX 128
#define SENT    0x7FFFFFFF

static const float R2F = (float)(0.08 * 0.08);

// -------- scratch (static device globals: allocation-free) --------
__device__ int    g_cell_scr[2 * NCELLS];     // [0,NCELLS): counts, [NCELLS,2N): fill cursors
__device__ int    g_cell_start[NCELLS + 1];
__device__ float4 g_sorted[N_PTS];            // (x,y,z, bitcast(orig index))
__device__ float4 g_featT[N_PTS * (C_FEAT / 4)];  // transposed features, (N, C) row-major

__device__ __forceinline__ int cell_of(float v) {
    int c = (int)(v * (float)NC);
    return min(max(c, 0), NC - 1);
}

// exact-match helpers: left-to-right fp32, no FMA contraction
__device__ __forceinline__ float sq3(float a, float b, float c) {
    return __fadd_rn(__fadd_rn(__fmul_rn(a, a), __fmul_rn(b, b)), __fmul_rn(c, c));
}
__device__ __forceinline__ float dot3(float ax, float ay, float az,
                                      float bx, float by, float bz) {
    return __fadd_rn(__fadd_rn(__fmul_rn(ax, bx), __fmul_rn(ay, by)), __fmul_rn(az, bz));
}

// -------- K0: zero grid scratch --------
__global__ void zero_kernel() {
    int i = blockIdx.x * blockDim.x + threadIdx.x;
    if (i < 2 * NCELLS) g_cell_scr[i] = 0;
}

// -------- K1: transpose features (C,N) -> (N,C) --------
__global__ void transpose_kernel(const float* __restrict__ feat) {
    __shared__ float tile[32][33];
    float* featT = (float*)g_featT;
    int n  = blockIdx.x * 32 + threadIdx.x;
    int c0 = blockIdx.y * 32 + threadIdx.y;
    #pragma unroll
    for (int k = 0; k < 32; k += 8) {
        int c = c0 + k;
        if (n < N_PTS && c < C_FEAT)
            tile[threadIdx.y + k][threadIdx.x] = feat[(size_t)c * N_PTS + n];
    }
    __syncthreads();
    int c2 = blockIdx.y * 32 + threadIdx.x;
    int n2 = blockIdx.x * 32 + threadIdx.y;
    #pragma unroll
    for (int k = 0; k < 32; k += 8) {
        int n3 = n2 + k;
        if (n3 < N_PTS && c2 < C_FEAT)
            featT[(size_t)n3 * C_FEAT + c2] = tile[threadIdx.x][threadIdx.y + k];
    }
}

// -------- K2: count points per cell --------
__global__ void count_kernel(const float* __restrict__ xyz) {
    int n = blockIdx.x * blockDim.x + threadIdx.x;
    if (n >= N_PTS) return;
    float x = xyz[3 * n], y = xyz[3 * n + 1], z = xyz[3 * n + 2];
    int cell = (cell_of(z) * NC + cell_of(y)) * NC + cell_of(x);
    atomicAdd(&g_cell_scr[cell], 1);
}

// -------- K3: exclusive scan over cell counts (single block) --------
__global__ void scan_kernel() {
    __shared__ int bufA[2048], bufB[2048];
    int t = threadIdx.x;  // 1024 threads
    for (int i = t; i < 2048; i += 1024) bufA[i] = (i < NCELLS) ? g_cell_scr[i] : 0;
    __syncthreads();
    int* src = bufA; int* dst = bufB;
    for (int off = 1; off < 2048; off <<= 1) {
        for (int i = t; i < 2048; i += 1024)
            dst[i] = src[i] + (i >= off ? src[i - off] : 0);
        __syncthreads();
        int* tmp = src; src = dst; dst = tmp;
    }
    for (int i = t; i < 2048; i += 1024)
        if (i < NCELLS) g_cell_start[i + 1] = src[i];
    if (t == 0) g_cell_start[0] = 0;
}

// -------- K4: scatter points into sorted-by-cell order --------
__global__ void scatter_kernel(const float* __restrict__ xyz) {
    int n = blockIdx.x * blockDim.x + threadIdx.x;
    if (n >= N_PTS) return;
    float x = xyz[3 * n], y = xyz[3 * n + 1], z = xyz[3 * n + 2];
    int cell = (cell_of(z) * NC + cell_of(y)) * NC + cell_of(x);
    int pos = g_cell_start[cell] + atomicAdd(&g_cell_scr[NCELLS + cell], 1);
    g_sorted[pos] = make_float4(x, y, z, __int_as_float(n));
}

// -------- K5: ball query (grid) + group, one warp per query --------
__global__ __launch_bounds__(256) void query_group_kernel(
    const float* __restrict__ new_xyz,
    const float* __restrict__ xyz,
    float* __restrict__ out,
    int write_idn)
{
    const int WPB = 8;
    __shared__ int cand[WPB][CAND_MAX];
    int w    = threadIdx.x >> 5;
    int lane = threadIdx.x & 31;
    int q = blockIdx.x * WPB + w;
    if (q >= NQ) return;
    int b = q >> 11;            // NQ_P == 2048
    int p = q & (NQ_P - 1);

    float qx = new_xyz[3 * q], qy = new_xyz[3 * q + 1], qz = new_xyz[3 * q + 2];
    float q2 = sq3(qx, qy, qz);
    const float R2 = R2F;
    const float rp = 0.0801f;   // padded radius for cell coverage

    int x0 = max(0,      (int)floorf((qx - rp) * (float)NC));
    int x1 = min(NC - 1, (int)floorf((qx + rp) * (float)NC));
    int y0 = max(0,      (int)floorf((qy - rp) * (float)NC));
    int y1 = min(NC - 1, (int)floorf((qy + rp) * (float)NC));
    int z0 = max(0,      (int)floorf((qz - rp) * (float)NC));
    int z1 = min(NC - 1, (int)floorf((qz + rp) * (float)NC));

    int base = 0;
    for (int cz = z0; cz <= z1; cz++) {
        for (int cy = y0; cy <= y1; cy++) {
            int crow = (cz * NC + cy) * NC;
            // cells x0..x1 are contiguous in the sorted array -> one scan range
            int s0 = g_cell_start[crow + x0];
            int s1 = g_cell_start[crow + x1 + 1];
            for (int j0 = s0; j0 < s1; j0 += 32) {
                int j = j0 + lane;
                bool inb = false; int pid = 0;
                if (j < s1) {
                    float4 pt = g_sorted[j];
                    float x2  = sq3(pt.x, pt.y, pt.z);
                    float dt  = dot3(qx, qy, qz, pt.x, pt.y, pt.z);
                    float d2  = __fsub_rn(__fadd_rn(q2, x2), __fmul_rn(2.0f, dt));
                    inb = d2 < R2;
                    pid = __float_as_int(pt.w);
                }
                unsigned m = __ballot_sync(0xffffffffu, inb);
                if (inb) {
                    int pos = base + __popc(m & ((1u << lane) - 1u));
                    if (pos < CAND_MAX) cand[w][pos] = pid;
                }
                base += __popc(m);
            }
        }
    }
    __syncwarp();

    int M = min(base, CAND_MAX);
    const int NCH = CAND_MAX / 32;  // 4
    int v[NCH];
    #pragma unroll
    for (int t = 0; t < NCH; t++)
        v[t] = (lane + 32 * t < M) ? cand[w][lane + 32 * t] : SENT;

    // extract the 32 smallest indices in ascending order; lane k keeps the k-th
    int sel = SENT;
    for (int k = 0; k < NSAMP; k++) {
        int lmin = SENT, tpos = 0;
        #pragma unroll
        for (int t = 0; t < NCH; t++)
            if (v[t] < lmin) { lmin = v[t]; tpos = t; }
        int g = lmin;
        #pragma unroll
        for (int o = 16; o; o >>= 1)
            g = min(g, __shfl_xor_sync(0xffffffffu, g, o));
        unsigned own = __ballot_sync(0xffffffffu, (lmin == g) && (g < SENT));
        if (own && lane == (__ffs(own) - 1)) v[tpos] = SENT;
        if (lane == k) sel = g;
    }

    unsigned vm = __ballot_sync(0xffffffffu, sel != SENT);
    int cnt   = __popc(vm);
    int first = __shfl_sync(0xffffffffu, sel, 0);
    bool valid = lane < cnt;
    int  id  = valid ? sel : (cnt ? first : 0);
    float idn = (valid || cnt == 0) ? 1.0f : 0.0f;

    // ---- group: lane = sample slot s ----
    float px = xyz[3 * id], py = xyz[3 * id + 1], pz = xyz[3 * id + 2];
    size_t ob = (((size_t)b * C_OUT) * NQ_P + (size_t)p) * NSAMP + (size_t)lane;
    const size_t st = (size_t)NQ_P * NSAMP;
    out[ob]          = __fsub_rn(px, qx);
    out[ob + st]     = __fsub_rn(py, qy);
    out[ob + 2 * st] = __fsub_rn(pz, qz);

    const float4* fr = g_featT + (size_t)id * (C_FEAT / 4);
    size_t o = ob + 3 * st;
    #pragma unroll
    for (int jj = 0; jj < C_FEAT / 4; jj++) {
        float4 f = fr[jj];
        out[o]          = f.x;
        out[o + st]     = f.y;
        out[o + 2 * st] = f.z;
        out[o + 3 * st] = f.w;
        o += 4 * st;
    }

    if (write_idn) {
        size_t nfe = (size_t)BATCH * C_OUT * NQ_P * NSAMP;
        out[nfe + (size_t)q * NSAMP + lane] = idn;
    }
}

extern "C" void kernel_launch(void* const* d_in, const int* in_sizes, int n_in,
                              void* d_out, int out_size) {
    const float* xyz     = (const float*)d_in[0];   // (20000, 3)
    const float* new_xyz = (const float*)d_in[1];   // (2, 2048, 3)
    const float* feat    = (const float*)d_in[2];   // (64, 20000)
    float* out = (float*)d_out;

    long long nfe = (long long)BATCH * C_OUT * NQ_P * NSAMP;           // 18,350,080
    int write_idn = ((long long)out_size >= nfe + (long long)NQ * NSAMP) ? 1 : 0;

    zero_kernel<<<(2 * NCELLS + 255) / 256, 256>>>();
    transpose_kernel<<<dim3((N_PTS + 31) / 32, (C_FEAT + 31) / 32), dim3(32, 8)>>>(feat);
    count_kernel<<<(N_PTS + 255) / 256, 256>>>(xyz);
    scan_kernel<<<1, 1024>>>();
    scatter_kernel<<<(N_PTS + 255) / 256, 256>>>(xyz);
    query_group_kernel<<<NQ / 8, 256>>>(new_xyz, xyz, out, write_idn);
}

// round 5
// speedup vs baseline: 1.2241x; 1.2241x over previous
#include <cuda_runtime.h>
#include <cstdint>

// Problem constants (fixed shapes from setup_inputs)
#define N_PTS   20000
#define C_FEAT  64
#define BATCH   2
#define NQ_P    2048
#define NSAMP   32
#define C_OUT   (3 + C_FEAT)          // 67
#define NQ      (BATCH * NQ_P)        // 4096
#define NC      12                    // grid cells per dim, cell = 1/12 >= radius
#define NCELLS  (NC * NC * NC)        // 1728
#define CAND_MAX 128
#define SENT    0x7FFFFFFF

static const float R2F = (float)(0.08 * 0.08);

// -------- scratch (static device globals: allocation-free) --------
// Invariant: g_cell_scr[0..NCELLS) (counts) is ZERO at kernel_launch entry.
// BSS-zeroed at load; scan_kernel re-zeroes after consuming each call.
__device__ int    g_cell_scr[2 * NCELLS];     // [0,NCELLS): counts, [NCELLS,2N): fill cursors
__device__ int    g_cell_start[NCELLS + 1];
__device__ float4 g_sorted[N_PTS];            // (x,y,z, bitcast(orig index))
__device__ float4 g_featT[N_PTS * (C_FEAT / 4)];  // transposed features, (N, C) row-major

__device__ __forceinline__ int cell_of(float v) {
    int c = (int)(v * (float)NC);
    return min(max(c, 0), NC - 1);
}

// exact-match helpers: left-to-right fp32, no FMA contraction
__device__ __forceinline__ float sq3(float a, float b, float c) {
    return __fadd_rn(__fadd_rn(__fmul_rn(a, a), __fmul_rn(b, b)), __fmul_rn(c, c));
}
__device__ __forceinline__ float dot3(float ax, float ay, float az,
                                      float bx, float by, float bz) {
    return __fadd_rn(__fadd_rn(__fmul_rn(ax, bx), __fmul_rn(ay, by)), __fmul_rn(az, bz));
}

// -------- K1: fused transpose (C,N)->(N,C)  +  per-cell count --------
#define T_BLOCKS_X 625                      // ceil(20000/32)
#define T_BLOCKS   (T_BLOCKS_X * 2)         // 2 channel tiles of 32
#define CNT_BLOCKS ((N_PTS + 255) / 256)    // 79

__global__ __launch_bounds__(256) void prep_kernel(const float* __restrict__ feat,
                                                   const float* __restrict__ xyz) {
    int bid = blockIdx.x;
    int tid = threadIdx.x;
    if (bid < T_BLOCKS) {
        // ---- transpose tile ----
        __shared__ float tile[32][33];
        float* featT = (float*)g_featT;
        int bx = bid % T_BLOCKS_X, by = bid / T_BLOCKS_X;
        int tx = tid & 31, ty = tid >> 5;           // 32 x 8
        int n  = bx * 32 + tx;
        int c0 = by * 32 + ty;
        #pragma unroll
        for (int k = 0; k < 32; k += 8) {
            int c = c0 + k;
            if (n < N_PTS && c < C_FEAT)
                tile[ty + k][tx] = feat[(size_t)c * N_PTS + n];
        }
        __syncthreads();
        int c2 = by * 32 + tx;
        int n2 = bx * 32 + ty;
        #pragma unroll
        for (int k = 0; k < 32; k += 8) {
            int n3 = n2 + k;
            if (n3 < N_PTS && c2 < C_FEAT)
                featT[(size_t)n3 * C_FEAT + c2] = tile[tx][ty + k];
        }
    } else {
        // ---- count points per cell ----
        int n = (bid - T_BLOCKS) * 256 + tid;
        if (n >= N_PTS) return;
        float x = xyz[3 * n], y = xyz[3 * n + 1], z = xyz[3 * n + 2];
        int cell = (cell_of(z) * NC + cell_of(y)) * NC + cell_of(x);
        atomicAdd(&g_cell_scr[cell], 1);
    }
}

// -------- K2: warp-shuffle exclusive scan (1 block, 1024 thr, 2 cells/thr) ----
// Also: zeroes counts (restores invariant for next replay) and zeroes the
// scatter cursors (consumed later this replay).
__global__ __launch_bounds__(1024) void scan_kernel() {
    __shared__ int wtot[32];
    __shared__ int woff[32];
    int t    = threadIdx.x;
    int lane = t & 31;
    int wid  = t >> 5;
    int i0 = 2 * t, i1 = 2 * t + 1;

    int c0 = (i0 < NCELLS) ? g_cell_scr[i0] : 0;
    int c1 = (i1 < NCELLS) ? g_cell_scr[i1] : 0;
    int s  = c0 + c1;

    // inclusive warp scan of s
    int incl = s;
    #pragma unroll
    for (int o = 1; o < 32; o <<= 1) {
        int nb = __shfl_up_sync(0xffffffffu, incl, o);
        if (lane >= o) incl += nb;
    }
    if (lane == 31) wtot[wid] = incl;
    __syncthreads();
    if (wid == 0) {
        int v = wtot[lane];
        int iv = v;
        #pragma unroll
        for (int o = 1; o < 32; o <<= 1) {
            int nb = __shfl_up_sync(0xffffffffu, iv, o);
            if (lane >= o) iv += nb;
        }
        woff[lane] = iv - v;    // exclusive warp offsets
    }
    __syncthreads();

    int ex = woff[wid] + incl - s;          // exclusive prefix before cell i0
    if (i0 < NCELLS) g_cell_start[i0] = ex;
    if (i1 < NCELLS) g_cell_start[i1] = ex + c0;
    if (i1 == NCELLS - 1) g_cell_start[NCELLS] = ex + c0 + c1;

    // restore zeros: counts (next replay) + cursors (this replay's scatter)
    if (i0 < NCELLS) { g_cell_scr[i0] = 0; g_cell_scr[NCELLS + i0] = 0; }
    if (i1 < NCELLS) { g_cell_scr[i1] = 0; g_cell_scr[NCELLS + i1] = 0; }
}

// -------- K3: scatter points into sorted-by-cell order --------
__global__ __launch_bounds__(256) void scatter_kernel(const float* __restrict__ xyz) {
    int n = blockIdx.x * blockDim.x + threadIdx.x;
    if (n >= N_PTS) return;
    float x = xyz[3 * n], y = xyz[3 * n + 1], z = xyz[3 * n + 2];
    int cell = (cell_of(z) * NC + cell_of(y)) * NC + cell_of(x);
    int pos = g_cell_start[cell] + atomicAdd(&g_cell_scr[NCELLS + cell], 1);
    g_sorted[pos] = make_float4(x, y, z, __int_as_float(n));
}

// -------- selection: 32 smallest indices ascending, lane k keeps the k-th ----
template <int NCHT>
__device__ __forceinline__ int select32(int* vv, int lane) {
    int sel = SENT;
    for (int k = 0; k < NSAMP; k++) {
        int lmin = SENT, tpos = 0;
        #pragma unroll
        for (int t = 0; t < NCHT; t++)
            if (vv[t] < lmin) { lmin = vv[t]; tpos = t; }
        unsigned g = __reduce_min_sync(0xffffffffu, (unsigned)lmin);
        if ((int)g == SENT) break;          // uniform: all exhausted
        unsigned own = __ballot_sync(0xffffffffu, (unsigned)lmin == g);
        if (own && lane == (__ffs(own) - 1)) vv[tpos] = SENT;
        if (lane == k) sel = (int)g;
    }
    return sel;
}

// -------- K4: ball query (grid) + group, one warp per query --------
#define WPB 4
__global__ __launch_bounds__(WPB * 32) void query_group_kernel(
    const float* __restrict__ new_xyz,
    const float* __restrict__ xyz,
    float* __restrict__ out,
    int write_idn)
{
    __shared__ int    cand[WPB][CAND_MAX];
    __shared__ float4 sbuf[WPB][NSAMP * 16];     // 8KB/warp staging (swizzled)
    int w    = threadIdx.x >> 5;
    int lane = threadIdx.x & 31;
    int q = blockIdx.x * WPB + w;
    if (q >= NQ) return;
    int b = q >> 11;            // NQ_P == 2048
    int p = q & (NQ_P - 1);

    float qx = new_xyz[3 * q], qy = new_xyz[3 * q + 1], qz = new_xyz[3 * q + 2];
    float q2 = sq3(qx, qy, qz);
    const float R2 = R2F;
    const float rp = 0.0801f;   // padded radius for cell coverage

    int x0 = max(0,      (int)floorf((qx - rp) * (float)NC));
    int x1 = min(NC - 1, (int)floorf((qx + rp) * (float)NC));
    int y0 = max(0,      (int)floorf((qy - rp) * (float)NC));
    int y1 = min(NC - 1, (int)floorf((qy + rp) * (float)NC));
    int z0 = max(0,      (int)floorf((qz - rp) * (float)NC));
    int z1 = min(NC - 1, (int)floorf((qz + rp) * (float)NC));

    int base = 0;
    for (int cz = z0; cz <= z1; cz++) {
        for (int cy = y0; cy <= y1; cy++) {
            int crow = (cz * NC + cy) * NC;
            // cells x0..x1 are contiguous in the sorted array -> one scan range
            int s0 = g_cell_start[crow + x0];
            int s1 = g_cell_start[crow + x1 + 1];
            for (int j0 = s0; j0 < s1; j0 += 32) {
                int j = j0 + lane;
                bool inb = false; int pid = 0;
                if (j < s1) {
                    float4 pt = g_sorted[j];
                    float x2  = sq3(pt.x, pt.y, pt.z);
                    float dt  = dot3(qx, qy, qz, pt.x, pt.y, pt.z);
                    float d2  = __fsub_rn(__fadd_rn(q2, x2), __fmul_rn(2.0f, dt));
                    inb = d2 < R2;
                    pid = __float_as_int(pt.w);
                }
                unsigned m = __ballot_sync(0xffffffffu, inb);
                if (inb) {
                    int pos = base + __popc(m & ((1u << lane) - 1u));
                    if (pos < CAND_MAX) cand[w][pos] = pid;
                }
                base += __popc(m);
            }
        }
    }
    __syncwarp();

    int M = min(base, CAND_MAX);
    int v[4];
    #pragma unroll
    for (int t = 0; t < 4; t++)
        v[t] = (lane + 32 * t < M) ? cand[w][lane + 32 * t] : SENT;

    int sel;
    if (M <= 64) sel = select32<2>(v, lane);   // 99.9% of queries
    else         sel = select32<4>(v, lane);

    unsigned vm = __ballot_sync(0xffffffffu, sel != SENT);
    int cnt   = __popc(vm);
    int first = __shfl_sync(0xffffffffu, sel, 0);
    bool valid = lane < cnt;
    int  id  = valid ? sel : (cnt ? first : 0);
    float idn = (valid || cnt == 0) ? 1.0f : 0.0f;

    // ---- xyz part (3 channels), lane = sample slot ----
    float px = xyz[3 * id], py = xyz[3 * id + 1], pz = xyz[3 * id + 2];
    size_t ob = (((size_t)b * C_OUT) * NQ_P + (size_t)p) * NSAMP + (size_t)lane;
    const size_t st = (size_t)NQ_P * NSAMP;
    out[ob]          = __fsub_rn(px, qx);
    out[ob + st]     = __fsub_rn(py, qy);
    out[ob + 2 * st] = __fsub_rn(pz, qz);

    // ---- cooperative coalesced feature gather via swizzled smem ----
    // load: 2 rows (256B each) per instruction, 16 float4 chunks/row
    float4* mybuf = sbuf[w];
    #pragma unroll
    for (int it = 0; it < 16; it++) {
        int r = 2 * it + (lane >> 4);                  // sample row 0..31
        int id_r = __shfl_sync(0xffffffffu, id, r);
        int chunk = lane & 15;                         // float4 chunk in row
        float4 val = g_featT[(size_t)id_r * 16 + chunk];
        mybuf[r * 16 + (chunk ^ (r & 15))] = val;      // swizzled, conflict-free
    }
    __syncwarp();

    // read transposed: lane = sample, iterate channel quads
    size_t o = ob + 3 * st;
    #pragma unroll
    for (int cq = 0; cq < 16; cq++) {
        float4 f = mybuf[lane * 16 + (cq ^ (lane & 15))];   // channels 4cq..4cq+3
        size_t oo = o + (size_t)(4 * cq) * st;
        out[oo]          = f.x;
        out[oo + st]     = f.y;
        out[oo + 2 * st] = f.z;
        out[oo + 3 * st] = f.w;
    }

    if (write_idn) {
        size_t nfe = (size_t)BATCH * C_OUT * NQ_P * NSAMP;
        out[nfe + (size_t)q * NSAMP + lane] = idn;
    }
}

extern "C" void kernel_launch(void* const* d_in, const int* in_sizes, int n_in,
                              void* d_out, int out_size) {
    const float* xyz     = (const float*)d_in[0];   // (20000, 3)
    const float* new_xyz = (const float*)d_in[1];   // (2, 2048, 3)
    const float* feat    = (const float*)d_in[2];   // (64, 20000)
    float* out = (float*)d_out;

    long long nfe = (long long)BATCH * C_OUT * NQ_P * NSAMP;           // 18,350,080
    int write_idn = ((long long)out_size >= nfe + (long long)NQ * NSAMP) ? 1 : 0;

    prep_kernel<<<T_BLOCKS + CNT_BLOCKS, 256>>>(feat, xyz);   // transpose + count (fused)
    scan_kernel<<<1, 1024>>>();                               // scan + re-zero scratch
    scatter_kernel<<<CNT_BLOCKS, 256>>>(xyz);
    query_group_kernel<<<NQ / WPB, WPB * 32>>>(new_xyz, xyz, out, write_idn);
}